// round 8
// baseline (speedup 1.0000x reference)
#include <cuda_runtime.h>
#include <cstdint>
#include <math.h>

// Problem dims
#define BB 64
#define TT 4096
#define HH 256
#define II 7
#define XD 12   // I + F

#define NRNN 32              // RNN CTAs, 2 chains each (interleaved, not fused)
#define NWORK 116
#define NCTA (NRNN + NWORK)  // 148
#define NT2 256

// ---------------- device scratch ----------------------------------------------
__device__ float g_ht[(size_t)BB * TT * HH];   // RNN hidden states (256 MB)
__device__ float g_xw[(size_t)BB * TT * HH];   // precomputed xW + biases (256 MB)
__device__ float g_wt[110520];                 // transposed MLP weights
__device__ int   g_prog[BB];                   // RNN progress per chain
__device__ int   g_tick;                       // MLP chunk ticket counter

// MLP layer offsets in g_wt
#define OFF0 0
#define OFF1 66816
#define OFF2 99584
#define OFF3 107776
#define OFF4 109824
#define OFF5 110336
#define OFF6 110464

// ---------------- helpers ------------------------------------------------------
__device__ __forceinline__ unsigned long long fma2(unsigned long long a,
                                                   unsigned long long b,
                                                   unsigned long long c) {
    unsigned long long d;
    asm("fma.rn.f32x2 %0, %1, %2, %3;" : "=l"(d) : "l"(a), "l"(b), "l"(c));
    return d;
}
__device__ __forceinline__ unsigned long long pack2(float lo, float hi) {
    unsigned long long d;
    asm("mov.b64 %0, {%1, %2};" : "=l"(d) : "f"(lo), "f"(hi));
    return d;
}
__device__ __forceinline__ float2 unpack2(unsigned long long v) {
    float lo, hi;
    asm("mov.b64 {%0, %1}, %2;" : "=f"(lo), "=f"(hi) : "l"(v));
    return make_float2(lo, hi);
}
__device__ __forceinline__ float rsum4(unsigned long long A, unsigned long long B) {
    float2 a = unpack2(A), b = unpack2(B);
    return (a.x + a.y) + (b.x + b.y);
}
__device__ __forceinline__ int ld_acquire(const int* p) {
    int v;
    asm volatile("ld.global.acquire.gpu.b32 %0, [%1];" : "=r"(v) : "l"(p));
    return v;
}
__device__ __forceinline__ void st_release(int* p, int v) {
    asm volatile("st.global.release.gpu.b32 [%0], %1;" :: "l"(p), "r"(v));
}
__device__ __forceinline__ float fast_tanh(float x) {
    float e = __expf(2.0f * x);
    return 1.0f - __fdividef(2.0f, e + 1.0f);
}
__device__ __forceinline__ void cpa16(uint32_t s, const void* g) {
    asm volatile("cp.async.cg.shared.global [%0], [%1], 16;" :: "r"(s), "l"(g));
}
__device__ __forceinline__ void cpa_commit() {
    asm volatile("cp.async.commit_group;" ::: "memory");
}

// ---------------- RNN config ---------------------------------------------------
// 256 threads/CTA, TWO chains per CTA processed sequentially per barrier.
// warp w, lane: q = lane>>3 (k-quarter), r = lane&7.
// Thread: rows j0..j0+3 (j0 = w*32 + r*4), k in [q*64, q*64+64).
// Per row: 48 weight floats in regs (96 ull total), 16 in smem.
#define RWP 48
#define SWP 16
#define WTST 68       // per-thread smem weight stride (64 used + 4 pad)
#define HQ 68         // h quarter stride (64 used + 4 pad)
#define HBF 272       // h buffer stride (4*HQ)
#define CH 16         // xw chunk (steps)
#define NCH (TT / CH) // 256

// smem: weights 256*68=17408 | xw 4*CH*HH=16384 | h 4*HBF=1088  => 34880 fl
#define RNN_SMF (NT2 * WTST + 4 * CH * HH + 4 * HBF)

// ---------------- MLP config ---------------------------------------------------
#define TOKN 64
#define TOKP 68
#define MLP_SMF ((264 + 256) * TOKP)                   // 35360 floats = 141440 B
#define FUSED_SMEM_B (MLP_SMF * 4)

template<int DOUT, int DIN, int TPG, bool LEAKY>
__device__ __forceinline__ void mlp_layer(const float* __restrict__ zin,
                                          float* __restrict__ zout,
                                          const float* __restrict__ wt,
                                          const float* __restrict__ bias)
{
    const int tid = threadIdx.x;
    const int o = tid % DOUT;
    const int g = tid / DOUT;

    if constexpr (TPG >= 4) {
        constexpr int NP = TPG / 2;
        unsigned long long acc[NP];
        #pragma unroll
        for (int p = 0; p < NP; p++) acc[p] = pack2(0.0f, 0.0f);
        #pragma unroll 4
        for (int k = 0; k < DIN; k++) {
            const float w = wt[k * DOUT + o];
            const unsigned long long w2 = pack2(w, w);
            const ulonglong2* zr = (const ulonglong2*)(zin + k * TOKP + g * TPG);
            #pragma unroll
            for (int p = 0; p < TPG / 4; p++) {
                ulonglong2 u = zr[p];
                acc[2 * p]     = fma2(w2, u.x, acc[2 * p]);
                acc[2 * p + 1] = fma2(w2, u.y, acc[2 * p + 1]);
            }
        }
        const float bv = bias[o];
        float* orow = zout + o * TOKP + g * TPG;
        #pragma unroll
        for (int p = 0; p < NP; p++) {
            float2 v = unpack2(acc[p]);
            v.x += bv; v.y += bv;
            if (LEAKY) { v.x = fmaxf(v.x, 0.01f * v.x); v.y = fmaxf(v.y, 0.01f * v.y); }
            orow[2 * p] = v.x; orow[2 * p + 1] = v.y;
        }
    } else if constexpr (TPG == 2) {
        unsigned long long acc = pack2(0.0f, 0.0f);
        #pragma unroll 4
        for (int k = 0; k < DIN; k++) {
            const float w = wt[k * DOUT + o];
            unsigned long long u = *(const unsigned long long*)(zin + k * TOKP + g * 2);
            acc = fma2(pack2(w, w), u, acc);
        }
        const float bv = bias[o];
        float2 v = unpack2(acc);
        v.x += bv; v.y += bv;
        if (LEAKY) { v.x = fmaxf(v.x, 0.01f * v.x); v.y = fmaxf(v.y, 0.01f * v.y); }
        float* orow = zout + o * TOKP + g * 2;
        orow[0] = v.x; orow[1] = v.y;
    }
}

// ---------------- RNN dot + reduce-scatter --------------------------------------
// Returns this thread's fully-reduced dot for row j0+q over all 256 k.
__device__ __forceinline__ float dot_reduce(
    const ulonglong2* __restrict__ h2,
    const unsigned long long* __restrict__ w0,
    const unsigned long long* __restrict__ w1,
    const unsigned long long* __restrict__ w2,
    const unsigned long long* __restrict__ w3,
    const ulonglong2* __restrict__ swp, int q)
{
    unsigned long long a0 = pack2(0.f, 0.f), a1 = a0, a2 = a0, a3 = a0;
    unsigned long long a4 = a0, a5 = a0, a6 = a0, a7 = a0;
    #pragma unroll
    for (int i = 0; i < RWP / 4; i++) {          // k_rel 0..47 (regs)
        ulonglong2 u = h2[i];
        a0 = fma2(w0[2 * i],     u.x, a0);
        a1 = fma2(w0[2 * i + 1], u.y, a1);
        a2 = fma2(w1[2 * i],     u.x, a2);
        a3 = fma2(w1[2 * i + 1], u.y, a3);
        a4 = fma2(w2[2 * i],     u.x, a4);
        a5 = fma2(w2[2 * i + 1], u.y, a5);
        a6 = fma2(w3[2 * i],     u.x, a6);
        a7 = fma2(w3[2 * i + 1], u.y, a7);
    }
    #pragma unroll
    for (int i = 0; i < SWP / 4; i++) {          // k_rel 48..63 (smem)
        ulonglong2 u = h2[RWP / 4 + i];
        ulonglong2 v0 = swp[0 + i];
        ulonglong2 v1 = swp[4 + i];
        ulonglong2 v2 = swp[8 + i];
        ulonglong2 v3 = swp[12 + i];
        a0 = fma2(v0.x, u.x, a0);
        a1 = fma2(v0.y, u.y, a1);
        a2 = fma2(v1.x, u.x, a2);
        a3 = fma2(v1.y, u.y, a3);
        a4 = fma2(v2.x, u.x, a4);
        a5 = fma2(v2.y, u.y, a5);
        a6 = fma2(v3.x, u.x, a6);
        a7 = fma2(v3.y, u.y, a7);
    }
    float p0 = rsum4(a0, a1);   // partial, row j0+0
    float p1 = rsum4(a2, a3);   // row j0+1
    float p2 = rsum4(a4, a5);   // row j0+2
    float p3 = rsum4(a6, a7);   // row j0+3
    // reduce-scatter: lane with quarter q ends with full sum of row j0+q.
    // Stage 1 (xor 8): pairs (q0,q1),(q2,q3). Even keeps rows {0,2}, odd {1,3}.
    const bool qb0 = (q & 1) != 0;
    const bool qb1 = (q & 2) != 0;
    float s1 = __shfl_xor_sync(0xFFFFFFFFu, qb0 ? p0 : p1, 8);
    float u0 = (qb0 ? p1 : p0) + s1;            // rows 1/0
    float s2 = __shfl_xor_sync(0xFFFFFFFFu, qb0 ? p2 : p3, 8);
    float u1 = (qb0 ? p3 : p2) + s2;            // rows 3/2
    // Stage 2 (xor 16): pairs (q0,q2),(q1,q3).
    float s3 = __shfl_xor_sync(0xFFFFFFFFu, qb1 ? u0 : u1, 16);
    return (qb1 ? u1 : u0) + s3;
}

// ---------------- RNN side: two chains per CTA, interleaved ---------------------
__device__ void rnn_cta(const float* __restrict__ W_hh, float* __restrict__ out,
                        float* sm, int cta)
{
    float* ws  = sm;                          // NT2*WTST
    float* xws = sm + NT2 * WTST;             // [chain][buf][CH*HH]
    float* hb  = xws + 4 * CH * HH;           // [chain][buf][HBF]
    const int b0 = 2 * cta, b1 = 2 * cta + 1;
    const int tid = threadIdx.x;
    const int w = tid >> 5, lane = tid & 31;
    const int q = lane >> 3, r = lane & 7;
    const int j0 = w * 32 + r * 4;
    const int myrow = j0 + q;
    const int hoff = (myrow >> 6) * HQ + (myrow & 63);

    // register weights: 4 rows x 48 floats (shared by both chains)
    unsigned long long w0[RWP / 2], w1[RWP / 2], w2[RWP / 2], w3[RWP / 2];
    {
        const ulonglong2* p0 = (const ulonglong2*)(W_hh + (j0 + 0) * HH + q * 64);
        const ulonglong2* p1 = (const ulonglong2*)(W_hh + (j0 + 1) * HH + q * 64);
        const ulonglong2* p2 = (const ulonglong2*)(W_hh + (j0 + 2) * HH + q * 64);
        const ulonglong2* p3 = (const ulonglong2*)(W_hh + (j0 + 3) * HH + q * 64);
        #pragma unroll
        for (int i = 0; i < RWP / 4; i++) {
            ulonglong2 u;
            u = p0[i]; w0[2 * i] = u.x; w0[2 * i + 1] = u.y;
            u = p1[i]; w1[2 * i] = u.x; w1[2 * i + 1] = u.y;
            u = p2[i]; w2[2 * i] = u.x; w2[2 * i + 1] = u.y;
            u = p3[i]; w3[2 * i] = u.x; w3[2 * i + 1] = u.y;
        }
    }
    // smem weights: 4 rows x 16 floats
    #pragma unroll
    for (int rr = 0; rr < 4; rr++) {
        const float4* gsrc = (const float4*)(W_hh + (j0 + rr) * HH + q * 64 + RWP);
        float4* dst = (float4*)(ws + tid * WTST + rr * SWP);
        #pragma unroll
        for (int i = 0; i < SWP / 4; i++) dst[i] = gsrc[i];
    }

    for (int idx = tid; idx < 4 * HBF; idx += NT2) hb[idx] = 0.0f;

    const float* xgA = g_xw + (size_t)b0 * TT * HH;
    const float* xgB = g_xw + (size_t)b1 * TT * HH;
    float* houtA = g_ht + (size_t)b0 * TT * HH;
    float* houtB = g_ht + (size_t)b1 * TT * HH;
    const uint32_t xw_sbase = (uint32_t)__cvta_generic_to_shared(xws);
    #define XWO(chain, buf) ((uint32_t)(((chain) * 2 + (buf)) * CH * HH))

    // prologue: stage chunk 0 and 1 for both chains (CH*HH = 4096 floats)
    #pragma unroll
    for (int i = 0; i < 4; i++) {
        cpa16(xw_sbase + (XWO(0, 0) / 4 + tid + i * NT2) * 16,
              (const float4*)xgA + tid + i * NT2);
        cpa16(xw_sbase + (XWO(1, 0) / 4 + tid + i * NT2) * 16,
              (const float4*)xgB + tid + i * NT2);
    }
    cpa_commit();
    #pragma unroll
    for (int i = 0; i < 4; i++) {
        cpa16(xw_sbase + (XWO(0, 1) / 4 + tid + i * NT2) * 16,
              (const float4*)(xgA + CH * HH) + tid + i * NT2);
        cpa16(xw_sbase + (XWO(1, 1) / 4 + tid + i * NT2) * 16,
              (const float4*)(xgB + CH * HH) + tid + i * NT2);
    }
    cpa_commit();

    int buf = 0;
    float hlA = 0.0f, hlB = 0.0f;
    const ulonglong2* swp = (const ulonglong2*)(ws + tid * WTST);
    float* hbA = hb;
    float* hbB = hb + 2 * HBF;

    for (int c = 0; c < NCH; c++) {
        if (c >= NCH - 2) { asm volatile("cp.async.wait_group 0;" ::: "memory"); }
        else              { asm volatile("cp.async.wait_group 1;" ::: "memory"); }
        __syncthreads();
        const float* xwcA = xws + XWO(0, c & 1);
        const float* xwcB = xws + XWO(1, c & 1);

        for (int s = 0; s < CH; s++) {
            const float xwA = xwcA[s * HH + myrow];
            const float xwB = xwcB[s * HH + myrow];
            const size_t t = (size_t)(c * CH + s);

            // ---- chain A step (reads hbA[buf], writes hbA[buf^1]) ----
            {
                const ulonglong2* hA2 =
                    (const ulonglong2*)(hbA + buf * HBF + q * HQ);
                const float sdA = dot_reduce(hA2, w0, w1, w2, w3, swp, q);
                const float hnA = fast_tanh(sdA + xwA);
                hbA[(buf ^ 1) * HBF + hoff] = hnA;
                houtA[t * HH + myrow] = hnA;
                hlA = hnA;
            }
            // ---- chain B step (independent of A's tail) ----
            {
                const ulonglong2* hB2 =
                    (const ulonglong2*)(hbB + buf * HBF + q * HQ);
                const float sdB = dot_reduce(hB2, w0, w1, w2, w3, swp, q);
                const float hnB = fast_tanh(sdB + xwB);
                hbB[(buf ^ 1) * HBF + hoff] = hnB;
                houtB[t * HH + myrow] = hnB;
                hlB = hnB;
            }
            __syncthreads();
            buf ^= 1;
        }

        if (tid == 0) st_release(&g_prog[b0], (c + 1) * CH);
        if (tid == 1) st_release(&g_prog[b1], (c + 1) * CH);

        if (c + 2 < NCH) {
            const float4* gA = (const float4*)(xgA + (size_t)(c + 2) * CH * HH);
            const float4* gB = (const float4*)(xgB + (size_t)(c + 2) * CH * HH);
            const uint32_t sbA = xw_sbase + XWO(0, c & 1) * 4;
            const uint32_t sbB = xw_sbase + XWO(1, c & 1) * 4;
            #pragma unroll
            for (int i = 0; i < 4; i++) {
                cpa16(sbA + (uint32_t)(tid + i * NT2) * 16, gA + tid + i * NT2);
                cpa16(sbB + (uint32_t)(tid + i * NT2) * 16, gB + tid + i * NT2);
            }
            cpa_commit();
        }
    }
    out[(size_t)BB * TT * II + (size_t)b0 * HH + myrow] = hlA;
    out[(size_t)BB * TT * II + (size_t)b1 * HH + myrow] = hlB;
    asm volatile("cp.async.wait_group 0;" ::: "memory");
    __syncthreads();
    #undef XWO
}

// ---------------- MLP worker ----------------------------------------------------
__device__ void mlp_worker(
    const float* __restrict__ x,
    const float* __restrict__ b0, const float* __restrict__ b1,
    const float* __restrict__ b2, const float* __restrict__ b3,
    const float* __restrict__ b4, const float* __restrict__ b5,
    const float* __restrict__ b6, float* __restrict__ out,
    float* sm)
{
    __shared__ int s_blk;
    float* bufA = sm;
    float* bufB = sm + 264 * TOKP;
    const int tid = threadIdx.x;

    for (;;) {
        __syncthreads();
        if (tid == 0) s_blk = atomicAdd(&g_tick, 1);
        __syncthreads();
        const int blk = s_blk;
        if (blk >= 64 * BB) return;
        const int tc = blk >> 6;       // chunk of 64 steps
        const int b = blk & 63;        // chain
        const int need = (tc + 1) * 64;

        if (tid == 0) {
            while (ld_acquire(&g_prog[b]) < need) __nanosleep(128);
        }
        __syncthreads();

        const size_t tok0 = (size_t)b * TT + (size_t)tc * TOKN;

        for (int idx = tid; idx < TOKN * 256; idx += NT2) {
            const int tk = idx >> 8, jj = idx & 255;
            bufA[jj * TOKP + tk] = g_ht[(tok0 + tk) * HH + jj];
        }
        for (int idx = tid; idx < TOKN * 5; idx += NT2) {
            const int tk = idx / 5, i = idx - tk * 5;
            bufA[(256 + i) * TOKP + tk] = x[(tok0 + tk) * XD + II + i];
        }
        __syncthreads();

        mlp_layer<256, 261, 64, true>(bufA, bufB, g_wt + OFF0, b0); __syncthreads();
        mlp_layer<128, 256, 32, true>(bufB, bufA, g_wt + OFF1, b1); __syncthreads();
        mlp_layer< 64, 128, 16, true>(bufA, bufB, g_wt + OFF2, b2); __syncthreads();
        mlp_layer< 32,  64,  8, true>(bufB, bufA, g_wt + OFF3, b3); __syncthreads();
        mlp_layer< 16,  32,  4, true>(bufA, bufB, g_wt + OFF4, b4); __syncthreads();
        mlp_layer<  8,  16,  2, true>(bufB, bufA, g_wt + OFF5, b5); __syncthreads();

        {
            const int o = tid & 7, g0 = tid >> 3;   // g0 in [0,32)
            if (o < 7) {
                #pragma unroll
                for (int g = g0; g < TOKN; g += 32) {
                    float acc = b6[o];
                    #pragma unroll
                    for (int k = 0; k < 8; k++)
                        acc = fmaf(g_wt[OFF6 + k * 7 + o], bufA[k * TOKP + g], acc);
                    out[(tok0 + g) * II + o] = acc;
                }
            }
        }
    }
}

// ---------------- fused kernel --------------------------------------------------
__global__ __launch_bounds__(NT2, 1) void fused_kernel(
    const float* __restrict__ x, const float* __restrict__ W_hh,
    const float* __restrict__ b0, const float* __restrict__ b1,
    const float* __restrict__ b2, const float* __restrict__ b3,
    const float* __restrict__ b4, const float* __restrict__ b5,
    const float* __restrict__ b6, float* __restrict__ out)
{
    extern __shared__ float sm[];
    if (blockIdx.x < NRNN) {
        rnn_cta(W_hh, out, sm, blockIdx.x);
        // chains finished -> join the MLP pool on this SM
        mlp_worker(x, b0, b1, b2, b3, b4, b5, b6, out, sm);
    } else {
        mlp_worker(x, b0, b1, b2, b3, b4, b5, b6, out, sm);
    }
}

// ---------------- xW precompute -------------------------------------------------
__global__ void xw_kernel(const float* __restrict__ x, const float* __restrict__ W_ih,
                          const float* __restrict__ b_ih, const float* __restrict__ b_hh)
{
    const int stride = gridDim.x * blockDim.x;
    for (size_t idx = (size_t)blockIdx.x * blockDim.x + threadIdx.x;
         idx < (size_t)BB * TT * HH; idx += stride) {
        const size_t tok = idx >> 8;
        const int j = (int)(idx & 255);
        const float* xr = x + tok * XD;
        float acc = b_ih[j] + b_hh[j];
        #pragma unroll
        for (int i = 0; i < II; i++) acc = fmaf(xr[i], W_ih[j * II + i], acc);
        g_xw[idx] = acc;
    }
}

// ---------------- prep ----------------------------------------------------------
__global__ void prep_kernel(const float* __restrict__ W0, const float* __restrict__ W1,
                            const float* __restrict__ W2, const float* __restrict__ W3,
                            const float* __restrict__ W4, const float* __restrict__ W5,
                            const float* __restrict__ W6)
{
    if (blockIdx.x == 0) {
        if (threadIdx.x < BB) g_prog[threadIdx.x] = 0;
        if (threadIdx.x == 0) g_tick = 0;
    }
    const float* Ws[7] = {W0, W1, W2, W3, W4, W5, W6};
    const int douts[7] = {256, 128, 64, 32, 16, 8, 7};
    const int dins[7]  = {261, 256, 128, 64, 32, 16, 8};
    int off = 0;
    const int stride = gridDim.x * blockDim.x;
    const int tid0 = blockIdx.x * blockDim.x + threadIdx.x;
    for (int l = 0; l < 7; l++) {
        const int dout = douts[l], din = dins[l], n = dout * din;
        const float* W = Ws[l];
        for (int idx = tid0; idx < n; idx += stride) {
            const int k = idx / dout, o = idx - k * dout;
            g_wt[off + idx] = W[o * din + k];
        }
        off += n;
    }
}

// ---------------- launch --------------------------------------------------------
extern "C" void kernel_launch(void* const* d_in, const int* in_sizes, int n_in,
                              void* d_out, int out_size)
{
    const float* x    = (const float*)d_in[0];
    const float* W_ih = (const float*)d_in[1];
    const float* W_hh = (const float*)d_in[2];
    const float* b_ih = (const float*)d_in[3];
    const float* b_hh = (const float*)d_in[4];
    const float* W[7];
    const float* bb[7];
    for (int i = 0; i < 7; i++) {
        W[i]  = (const float*)d_in[5 + 2 * i];
        bb[i] = (const float*)d_in[6 + 2 * i];
    }
    float* out = (float*)d_out;

    static int inited = 0;
    if (!inited) {
        cudaFuncSetAttribute(fused_kernel,
                             cudaFuncAttributeMaxDynamicSharedMemorySize, FUSED_SMEM_B);
        inited = 1;
    }

    prep_kernel<<<64, 256>>>(W[0], W[1], W[2], W[3], W[4], W[5], W[6]);
    xw_kernel<<<512, 256>>>(x, W_ih, b_ih, b_hh);
    fused_kernel<<<NCTA, NT2, FUSED_SMEM_B>>>(x, W_hh,
                                              bb[0], bb[1], bb[2], bb[3],
                                              bb[4], bb[5], bb[6], out);
}

// round 9
// speedup vs baseline: 1.0409x; 1.0409x over previous
#include <cuda_runtime.h>
#include <cstdint>
#include <math.h>

// Problem dims
#define BB 64
#define TT 4096
#define HH 256
#define II 7
#define XD 12   // I + F

#define NRNN 32              // RNN CTAs, 2 chains each (fused packed-row loop)
#define NWORK 116
#define NCTA (NRNN + NWORK)  // 148
#define NT2 256

// ---------------- device scratch ----------------------------------------------
__device__ float g_ht[(size_t)BB * TT * HH];   // RNN hidden states (256 MB)
__device__ float g_xw[(size_t)BB * TT * HH];   // precomputed xW + biases (256 MB)
__device__ float g_wt[110520];                 // transposed MLP weights
__device__ int   g_prog[BB];                   // RNN progress per chain
__device__ int   g_tick;                       // MLP chunk ticket counter

// MLP layer offsets in g_wt
#define OFF0 0
#define OFF1 66816
#define OFF2 99584
#define OFF3 107776
#define OFF4 109824
#define OFF5 110336
#define OFF6 110464

// ---------------- helpers ------------------------------------------------------
__device__ __forceinline__ unsigned long long fma2(unsigned long long a,
                                                   unsigned long long b,
                                                   unsigned long long c) {
    unsigned long long d;
    asm("fma.rn.f32x2 %0, %1, %2, %3;" : "=l"(d) : "l"(a), "l"(b), "l"(c));
    return d;
}
__device__ __forceinline__ unsigned long long pack2(float lo, float hi) {
    unsigned long long d;
    asm("mov.b64 %0, {%1, %2};" : "=l"(d) : "f"(lo), "f"(hi));
    return d;
}
__device__ __forceinline__ float2 unpack2(unsigned long long v) {
    float lo, hi;
    asm("mov.b64 {%0, %1}, %2;" : "=f"(lo), "=f"(hi) : "l"(v));
    return make_float2(lo, hi);
}
__device__ __forceinline__ int ld_acquire(const int* p) {
    int v;
    asm volatile("ld.global.acquire.gpu.b32 %0, [%1];" : "=r"(v) : "l"(p));
    return v;
}
__device__ __forceinline__ void st_release(int* p, int v) {
    asm volatile("st.global.release.gpu.b32 [%0], %1;" :: "l"(p), "r"(v));
}
__device__ __forceinline__ float fast_tanh(float x) {
    float e = __expf(2.0f * x);
    return 1.0f - __fdividef(2.0f, e + 1.0f);
}
__device__ __forceinline__ void cpa16(uint32_t s, const void* g) {
    asm volatile("cp.async.cg.shared.global [%0], [%1], 16;" :: "r"(s), "l"(g));
}
__device__ __forceinline__ void cpa_commit() {
    asm volatile("cp.async.commit_group;" ::: "memory");
}

// ---------------- RNN config ---------------------------------------------------
// 256 threads/CTA, TWO chains per CTA, fused in one inner loop.
// warp w, lane: q = lane>>3 (k-quarter), r = lane&7.
// Thread: rows j0..j0+3 (j0 = w*32 + r*4), k in [q*64, q*64+64), both chains.
// Weights PACKED BY ROW-PAIR: wp01[k]=(w_j0[k],w_j1[k]), wp23[k]=(w_j2[k],w_j3[k]).
// h stored DUPLICATED in smem: (h[k],h[k]) so fma2 accumulates 2 rows per ull.
#define RK 48          // k-values with register-resident packed weights
#define WTST 68        // per-thread smem weight stride (16 k * 4 fl = 64 + 4 pad)
#define HD2 136        // duplicated-h quarter stride (128 used + 8 pad)
#define HB2 544        // per-buffer h stride (4*HD2)
#define CH 8           // xw chunk (steps)
#define NCH (TT / CH)  // 512

// smem: weights 256*68=17408 | xw 4*CH*HH=8192 | h 2 chains*2 bufs*HB2=2176
#define RNN_SMF (NT2 * WTST + 4 * CH * HH + 4 * HB2)   // 27776 fl

// ---------------- MLP config ---------------------------------------------------
#define TOKN 64
#define TOKP 68
#define MLP_SMF ((264 + 256) * TOKP)                   // 35360 fl = 141440 B
#define FUSED_SMEM_B (MLP_SMF * 4)

template<int DOUT, int DIN, int TPG, bool LEAKY>
__device__ __forceinline__ void mlp_layer(const float* __restrict__ zin,
                                          float* __restrict__ zout,
                                          const float* __restrict__ wt,
                                          const float* __restrict__ bias)
{
    const int tid = threadIdx.x;
    const int o = tid % DOUT;
    const int g = tid / DOUT;

    if constexpr (TPG >= 4) {
        constexpr int NP = TPG / 2;
        unsigned long long acc[NP];
        #pragma unroll
        for (int p = 0; p < NP; p++) acc[p] = pack2(0.0f, 0.0f);
        #pragma unroll 4
        for (int k = 0; k < DIN; k++) {
            const float w = wt[k * DOUT + o];
            const unsigned long long w2 = pack2(w, w);
            const ulonglong2* zr = (const ulonglong2*)(zin + k * TOKP + g * TPG);
            #pragma unroll
            for (int p = 0; p < TPG / 4; p++) {
                ulonglong2 u = zr[p];
                acc[2 * p]     = fma2(w2, u.x, acc[2 * p]);
                acc[2 * p + 1] = fma2(w2, u.y, acc[2 * p + 1]);
            }
        }
        const float bv = bias[o];
        float* orow = zout + o * TOKP + g * TPG;
        #pragma unroll
        for (int p = 0; p < NP; p++) {
            float2 v = unpack2(acc[p]);
            v.x += bv; v.y += bv;
            if (LEAKY) { v.x = fmaxf(v.x, 0.01f * v.x); v.y = fmaxf(v.y, 0.01f * v.y); }
            orow[2 * p] = v.x; orow[2 * p + 1] = v.y;
        }
    } else if constexpr (TPG == 2) {
        unsigned long long acc = pack2(0.0f, 0.0f);
        #pragma unroll 4
        for (int k = 0; k < DIN; k++) {
            const float w = wt[k * DOUT + o];
            unsigned long long u = *(const unsigned long long*)(zin + k * TOKP + g * 2);
            acc = fma2(pack2(w, w), u, acc);
        }
        const float bv = bias[o];
        float2 v = unpack2(acc);
        v.x += bv; v.y += bv;
        if (LEAKY) { v.x = fmaxf(v.x, 0.01f * v.x); v.y = fmaxf(v.y, 0.01f * v.y); }
        float* orow = zout + o * TOKP + g * 2;
        orow[0] = v.x; orow[1] = v.y;
    }
}

// ---------------- RNN side ------------------------------------------------------
__device__ void rnn_cta(const float* __restrict__ W_hh, float* __restrict__ out,
                        float* sm, int cta)
{
    float* ws  = sm;                          // NT2*WTST
    float* xws = sm + NT2 * WTST;             // [chain][buf][CH*HH]
    float* hb  = xws + 4 * CH * HH;           // [chain][buf][HB2] duplicated h
    const int b0 = 2 * cta, b1 = 2 * cta + 1;
    const int tid = threadIdx.x;
    const int w = tid >> 5, lane = tid & 31;
    const int q = lane >> 3, r = lane & 7;
    const int j0 = w * 32 + r * 4;
    const int myrow = j0 + q;
    const int hoff = (myrow >> 6) * HD2 + (myrow & 63) * 2;  // duplicated slot
    const bool qb0 = (q & 1) != 0;
    const bool qb1 = (q & 2) != 0;

    // packed register weights: wp01/wp23 for k_rel 0..RK-1
    unsigned long long wp01[RK], wp23[RK];
    {
        const float* r0 = W_hh + (j0 + 0) * HH + q * 64;
        const float* r1 = W_hh + (j0 + 1) * HH + q * 64;
        const float* r2 = W_hh + (j0 + 2) * HH + q * 64;
        const float* r3 = W_hh + (j0 + 3) * HH + q * 64;
        #pragma unroll
        for (int i = 0; i < RK; i++) {
            wp01[i] = pack2(r0[i], r1[i]);
            wp23[i] = pack2(r2[i], r3[i]);
        }
        // smem packed weights: k_rel RK..63, layout per k: [w0,w1,w2,w3]
        for (int k = RK; k < 64; k++) {
            float* d = ws + tid * WTST + (k - RK) * 4;
            d[0] = r0[k]; d[1] = r1[k]; d[2] = r2[k]; d[3] = r3[k];
        }
    }

    for (int idx = tid; idx < 4 * HB2; idx += NT2) hb[idx] = 0.0f;

    const float* xgA = g_xw + (size_t)b0 * TT * HH;
    const float* xgB = g_xw + (size_t)b1 * TT * HH;
    float* houtA = g_ht + (size_t)b0 * TT * HH;
    float* houtB = g_ht + (size_t)b1 * TT * HH;
    const uint32_t xw_sbase = (uint32_t)__cvta_generic_to_shared(xws);
    #define XWO(chain, buf) ((uint32_t)(((chain) * 2 + (buf)) * CH * HH))

    // prologue: stage chunks 0 and 1 for both chains (CH*HH = 2048 fl = 512 f4)
    #pragma unroll
    for (int i = 0; i < 2; i++) {
        cpa16(xw_sbase + (XWO(0, 0) / 4 + tid + i * NT2) * 16,
              (const float4*)xgA + tid + i * NT2);
        cpa16(xw_sbase + (XWO(1, 0) / 4 + tid + i * NT2) * 16,
              (const float4*)xgB + tid + i * NT2);
    }
    cpa_commit();
    #pragma unroll
    for (int i = 0; i < 2; i++) {
        cpa16(xw_sbase + (XWO(0, 1) / 4 + tid + i * NT2) * 16,
              (const float4*)(xgA + CH * HH) + tid + i * NT2);
        cpa16(xw_sbase + (XWO(1, 1) / 4 + tid + i * NT2) * 16,
              (const float4*)(xgB + CH * HH) + tid + i * NT2);
    }
    cpa_commit();

    int buf = 0;
    float hlA = 0.0f, hlB = 0.0f;
    float* hbA = hb;
    float* hbB = hb + 2 * HB2;

    for (int c = 0; c < NCH; c++) {
        if (c >= NCH - 2) { asm volatile("cp.async.wait_group 0;" ::: "memory"); }
        else              { asm volatile("cp.async.wait_group 1;" ::: "memory"); }
        __syncthreads();
        const float* xwcA = xws + XWO(0, c & 1);
        const float* xwcB = xws + XWO(1, c & 1);

        for (int s = 0; s < CH; s++) {
            const float xwA = xwcA[s * HH + myrow];
            const float xwB = xwcB[s * HH + myrow];
            const ulonglong2* hA2 = (const ulonglong2*)(hbA + buf * HB2 + q * HD2);
            const ulonglong2* hB2 = (const ulonglong2*)(hbB + buf * HB2 + q * HD2);

            unsigned long long aA01 = pack2(0.f, 0.f), aA23 = aA01;
            unsigned long long aB01 = aA01, aB23 = aA01;

            #pragma unroll
            for (int i = 0; i < RK / 2; i++) {       // k_rel 2i, 2i+1 (regs)
                ulonglong2 uA = hA2[i];              // (h[2i]x2, h[2i+1]x2)
                ulonglong2 uB = hB2[i];
                aA01 = fma2(wp01[2 * i],     uA.x, aA01);
                aA23 = fma2(wp23[2 * i],     uA.x, aA23);
                aB01 = fma2(wp01[2 * i],     uB.x, aB01);
                aB23 = fma2(wp23[2 * i],     uB.x, aB23);
                aA01 = fma2(wp01[2 * i + 1], uA.y, aA01);
                aA23 = fma2(wp23[2 * i + 1], uA.y, aA23);
                aB01 = fma2(wp01[2 * i + 1], uB.y, aB01);
                aB23 = fma2(wp23[2 * i + 1], uB.y, aB23);
            }
            const ulonglong2* wk = (const ulonglong2*)(ws + tid * WTST);
            #pragma unroll
            for (int i = 0; i < (64 - RK) / 2; i++) {  // k_rel RK+2i, RK+2i+1 (smem)
                ulonglong2 uA = hA2[RK / 2 + i];
                ulonglong2 uB = hB2[RK / 2 + i];
                ulonglong2 w1 = wk[2 * i];             // (pair01, pair23) @ k=RK+2i
                ulonglong2 w2 = wk[2 * i + 1];
                aA01 = fma2(w1.x, uA.x, aA01);
                aA23 = fma2(w1.y, uA.x, aA23);
                aB01 = fma2(w1.x, uB.x, aB01);
                aB23 = fma2(w1.y, uB.x, aB23);
                aA01 = fma2(w2.x, uA.y, aA01);
                aA23 = fma2(w2.y, uA.y, aA23);
                aB01 = fma2(w2.x, uB.y, aB01);
                aB23 = fma2(w2.y, uB.y, aB23);
            }

            // partials: rows j0..j0+3 directly from packed accumulators
            float2 pA01 = unpack2(aA01), pA23 = unpack2(aA23);
            float2 pB01 = unpack2(aB01), pB23 = unpack2(aB23);

            // reduce-scatter over 4 q-lanes (validated in round 8)
            float sA1 = __shfl_xor_sync(0xFFFFFFFFu, qb0 ? pA01.x : pA01.y, 8);
            float uA0 = (qb0 ? pA01.y : pA01.x) + sA1;
            float sA2 = __shfl_xor_sync(0xFFFFFFFFu, qb0 ? pA23.x : pA23.y, 8);
            float uA1 = (qb0 ? pA23.y : pA23.x) + sA2;
            float sB1 = __shfl_xor_sync(0xFFFFFFFFu, qb0 ? pB01.x : pB01.y, 8);
            float uB0 = (qb0 ? pB01.y : pB01.x) + sB1;
            float sB2 = __shfl_xor_sync(0xFFFFFFFFu, qb0 ? pB23.x : pB23.y, 8);
            float uB1 = (qb0 ? pB23.y : pB23.x) + sB2;
            float sA3 = __shfl_xor_sync(0xFFFFFFFFu, qb1 ? uA0 : uA1, 16);
            float sdA = (qb1 ? uA1 : uA0) + sA3;
            float sB3 = __shfl_xor_sync(0xFFFFFFFFu, qb1 ? uB0 : uB1, 16);
            float sdB = (qb1 ? uB1 : uB0) + sB3;

            const float hnA = fast_tanh(sdA + xwA);
            const float hnB = fast_tanh(sdB + xwB);

            // duplicated h store (8B) + streamed ht
            *(float2*)(hbA + (buf ^ 1) * HB2 + hoff) = make_float2(hnA, hnA);
            *(float2*)(hbB + (buf ^ 1) * HB2 + hoff) = make_float2(hnB, hnB);
            const size_t t = (size_t)(c * CH + s);
            houtA[t * HH + myrow] = hnA;
            houtB[t * HH + myrow] = hnB;
            hlA = hnA; hlB = hnB;
            __syncthreads();
            buf ^= 1;
        }

        if (tid == 0) st_release(&g_prog[b0], (c + 1) * CH);
        if (tid == 1) st_release(&g_prog[b1], (c + 1) * CH);

        if (c + 2 < NCH) {
            const float4* gA = (const float4*)(xgA + (size_t)(c + 2) * CH * HH);
            const float4* gB = (const float4*)(xgB + (size_t)(c + 2) * CH * HH);
            const uint32_t sbA = xw_sbase + XWO(0, c & 1) * 4;
            const uint32_t sbB = xw_sbase + XWO(1, c & 1) * 4;
            #pragma unroll
            for (int i = 0; i < 2; i++) {
                cpa16(sbA + (uint32_t)(tid + i * NT2) * 16, gA + tid + i * NT2);
                cpa16(sbB + (uint32_t)(tid + i * NT2) * 16, gB + tid + i * NT2);
            }
            cpa_commit();
        }
    }
    out[(size_t)BB * TT * II + (size_t)b0 * HH + myrow] = hlA;
    out[(size_t)BB * TT * II + (size_t)b1 * HH + myrow] = hlB;
    asm volatile("cp.async.wait_group 0;" ::: "memory");
    __syncthreads();
    #undef XWO
}

// ---------------- MLP worker ----------------------------------------------------
__device__ void mlp_worker(
    const float* __restrict__ x,
    const float* __restrict__ b0, const float* __restrict__ b1,
    const float* __restrict__ b2, const float* __restrict__ b3,
    const float* __restrict__ b4, const float* __restrict__ b5,
    const float* __restrict__ b6, float* __restrict__ out,
    float* sm)
{
    __shared__ int s_blk;
    float* bufA = sm;
    float* bufB = sm + 264 * TOKP;
    const int tid = threadIdx.x;

    for (;;) {
        __syncthreads();
        if (tid == 0) s_blk = atomicAdd(&g_tick, 1);
        __syncthreads();
        const int blk = s_blk;
        if (blk >= 64 * BB) return;
        const int tc = blk >> 6;       // chunk of 64 steps
        const int b = blk & 63;        // chain
        const int need = (tc + 1) * 64;

        if (tid == 0) {
            while (ld_acquire(&g_prog[b]) < need) __nanosleep(128);
        }
        __syncthreads();

        const size_t tok0 = (size_t)b * TT + (size_t)tc * TOKN;

        for (int idx = tid; idx < TOKN * 256; idx += NT2) {
            const int tk = idx >> 8, jj = idx & 255;
            bufA[jj * TOKP + tk] = g_ht[(tok0 + tk) * HH + jj];
        }
        for (int idx = tid; idx < TOKN * 5; idx += NT2) {
            const int tk = idx / 5, i = idx - tk * 5;
            bufA[(256 + i) * TOKP + tk] = x[(tok0 + tk) * XD + II + i];
        }
        __syncthreads();

        mlp_layer<256, 261, 64, true>(bufA, bufB, g_wt + OFF0, b0); __syncthreads();
        mlp_layer<128, 256, 32, true>(bufB, bufA, g_wt + OFF1, b1); __syncthreads();
        mlp_layer< 64, 128, 16, true>(bufA, bufB, g_wt + OFF2, b2); __syncthreads();
        mlp_layer< 32,  64,  8, true>(bufB, bufA, g_wt + OFF3, b3); __syncthreads();
        mlp_layer< 16,  32,  4, true>(bufA, bufB, g_wt + OFF4, b4); __syncthreads();
        mlp_layer<  8,  16,  2, true>(bufB, bufA, g_wt + OFF5, b5); __syncthreads();

        {
            const int o = tid & 7, g0 = tid >> 3;   // g0 in [0,32)
            if (o < 7) {
                #pragma unroll
                for (int g = g0; g < TOKN; g += 32) {
                    float acc = b6[o];
                    #pragma unroll
                    for (int k = 0; k < 8; k++)
                        acc = fmaf(g_wt[OFF6 + k * 7 + o], bufA[k * TOKP + g], acc);
                    out[(tok0 + g) * II + o] = acc;
                }
            }
        }
    }
}

// ---------------- fused kernel --------------------------------------------------
__global__ __launch_bounds__(NT2, 1) void fused_kernel(
    const float* __restrict__ x, const float* __restrict__ W_hh,
    const float* __restrict__ b0, const float* __restrict__ b1,
    const float* __restrict__ b2, const float* __restrict__ b3,
    const float* __restrict__ b4, const float* __restrict__ b5,
    const float* __restrict__ b6, float* __restrict__ out)
{
    extern __shared__ float sm[];
    if (blockIdx.x < NRNN) {
        rnn_cta(W_hh, out, sm, blockIdx.x);
        // chains finished -> join the MLP pool on this SM
        mlp_worker(x, b0, b1, b2, b3, b4, b5, b6, out, sm);
    } else {
        mlp_worker(x, b0, b1, b2, b3, b4, b5, b6, out, sm);
    }
}

// ---------------- xW precompute -------------------------------------------------
__global__ void xw_kernel(const float* __restrict__ x, const float* __restrict__ W_ih,
                          const float* __restrict__ b_ih, const float* __restrict__ b_hh)
{
    const int stride = gridDim.x * blockDim.x;
    for (size_t idx = (size_t)blockIdx.x * blockDim.x + threadIdx.x;
         idx < (size_t)BB * TT * HH; idx += stride) {
        const size_t tok = idx >> 8;
        const int j = (int)(idx & 255);
        const float* xr = x + tok * XD;
        float acc = b_ih[j] + b_hh[j];
        #pragma unroll
        for (int i = 0; i < II; i++) acc = fmaf(xr[i], W_ih[j * II + i], acc);
        g_xw[idx] = acc;
    }
}

// ---------------- prep ----------------------------------------------------------
__global__ void prep_kernel(const float* __restrict__ W0, const float* __restrict__ W1,
                            const float* __restrict__ W2, const float* __restrict__ W3,
                            const float* __restrict__ W4, const float* __restrict__ W5,
                            const float* __restrict__ W6)
{
    if (blockIdx.x == 0) {
        if (threadIdx.x < BB) g_prog[threadIdx.x] = 0;
        if (threadIdx.x == 0) g_tick = 0;
    }
    const float* Ws[7] = {W0, W1, W2, W3, W4, W5, W6};
    const int douts[7] = {256, 128, 64, 32, 16, 8, 7};
    const int dins[7]  = {261, 256, 128, 64, 32, 16, 8};
    int off = 0;
    const int stride = gridDim.x * blockDim.x;
    const int tid0 = blockIdx.x * blockDim.x + threadIdx.x;
    for (int l = 0; l < 7; l++) {
        const int dout = douts[l], din = dins[l], n = dout * din;
        const float* W = Ws[l];
        for (int idx = tid0; idx < n; idx += stride) {
            const int k = idx / dout, o = idx - k * dout;
            g_wt[off + idx] = W[o * din + k];
        }
        off += n;
    }
}

// ---------------- launch --------------------------------------------------------
extern "C" void kernel_launch(void* const* d_in, const int* in_sizes, int n_in,
                              void* d_out, int out_size)
{
    const float* x    = (const float*)d_in[0];
    const float* W_ih = (const float*)d_in[1];
    const float* W_hh = (const float*)d_in[2];
    const float* b_ih = (const float*)d_in[3];
    const float* b_hh = (const float*)d_in[4];
    const float* W[7];
    const float* bb[7];
    for (int i = 0; i < 7; i++) {
        W[i]  = (const float*)d_in[5 + 2 * i];
        bb[i] = (const float*)d_in[6 + 2 * i];
    }
    float* out = (float*)d_out;

    static int inited = 0;
    if (!inited) {
        cudaFuncSetAttribute(fused_kernel,
                             cudaFuncAttributeMaxDynamicSharedMemorySize, FUSED_SMEM_B);
        inited = 1;
    }

    prep_kernel<<<64, 256>>>(W[0], W[1], W[2], W[3], W[4], W[5], W[6]);
    xw_kernel<<<512, 256>>>(x, W_ih, b_ih, b_hh);
    fused_kernel<<<NCTA, NT2, FUSED_SMEM_B>>>(x, W_hh,
                                              bb[0], bb[1], bb[2], bb[3],
                                              bb[4], bb[5], bb[6], out);
}

// round 10
// speedup vs baseline: 1.4699x; 1.4122x over previous
#include <cuda_runtime.h>
#include <cstdint>
#include <math.h>

// Problem dims
#define BB 64
#define TT 4096
#define HH 256
#define II 7
#define XD 12   // I + F

#define NRNN 64
#define NWORK 84
#define NCTA (NRNN + NWORK)
#define NT2 256

// ---------------- device scratch ----------------------------------------------
__device__ float g_ht[(size_t)BB * TT * HH];   // RNN hidden states (256 MB)
__device__ float g_xw[(size_t)BB * TT * HH];   // precomputed xW + biases (256 MB)
__device__ float g_wt[110520];                 // transposed MLP weights
__device__ int   g_prog[BB];                   // RNN progress per chain
__device__ int   g_tick;                       // MLP chunk ticket counter

// MLP layer offsets in g_wt
#define OFF0 0
#define OFF1 66816
#define OFF2 99584
#define OFF3 107776
#define OFF4 109824
#define OFF5 110336
#define OFF6 110464

// ---------------- helpers ------------------------------------------------------
__device__ __forceinline__ unsigned long long fma2(unsigned long long a,
                                                   unsigned long long b,
                                                   unsigned long long c) {
    unsigned long long d;
    asm("fma.rn.f32x2 %0, %1, %2, %3;" : "=l"(d) : "l"(a), "l"(b), "l"(c));
    return d;
}
__device__ __forceinline__ unsigned long long pack2(float lo, float hi) {
    unsigned long long d;
    asm("mov.b64 %0, {%1, %2};" : "=l"(d) : "f"(lo), "f"(hi));
    return d;
}
__device__ __forceinline__ float2 unpack2(unsigned long long v) {
    float lo, hi;
    asm("mov.b64 {%0, %1}, %2;" : "=f"(lo), "=f"(hi) : "l"(v));
    return make_float2(lo, hi);
}
__device__ __forceinline__ int ld_acquire(const int* p) {
    int v;
    asm volatile("ld.global.acquire.gpu.b32 %0, [%1];" : "=r"(v) : "l"(p));
    return v;
}
__device__ __forceinline__ void st_release(int* p, int v) {
    asm volatile("st.global.release.gpu.b32 [%0], %1;" :: "l"(p), "r"(v));
}
__device__ __forceinline__ float fast_tanh(float x) {
    float e = __expf(2.0f * x);
    return 1.0f - __fdividef(2.0f, e + 1.0f);
}
__device__ __forceinline__ void cpa16(uint32_t s, const void* g) {
    asm volatile("cp.async.cg.shared.global [%0], [%1], 16;" :: "r"(s), "l"(g));
}
__device__ __forceinline__ void cpa_commit() {
    asm volatile("cp.async.commit_group;" ::: "memory");
}

// ---------------- RNN config ---------------------------------------------------
// 256 threads, one CTA per chain. warp w = tid>>5; lane: g = lane>>2 (k-group of
// 32 k), rr = lane&3. Thread: rows j0..j0+7 (j0 = w*32 + rr*8), k in [g*32,+32).
// Per row: 24 weight floats in regs (12 ull), 8 in smem.
#define RKU 12        // reg ulls per row (24 k-values)
#define SWF 8         // smem weight floats per row (k_rel 24..31)
#define WTST 68       // per-thread smem weight stride (64 used + 4 pad)
#define HPAD 36       // h group stride (32 used + 4 pad) -> conflict-free
#define HBUF 288      // h buffer stride (8*HPAD)
#define CH 32         // xw chunk (steps)
#define NCH (TT / CH) // 128

// smem: weights 256*68=17408 | xw 2*CH*HH=16384 | h 2*HBUF=576 => 34368 fl
#define RNN_SMF (NT2 * WTST + 2 * CH * HH + 2 * HBUF)

// ---------------- MLP config ---------------------------------------------------
#define TOKN 64
#define TOKP 68
#define MLP_SMF ((264 + 256) * TOKP)                   // 35360 fl = 141440 B
#define FUSED_SMEM_B (MLP_SMF * 4)

template<int DOUT, int DIN, int TPG, bool LEAKY>
__device__ __forceinline__ void mlp_layer(const float* __restrict__ zin,
                                          float* __restrict__ zout,
                                          const float* __restrict__ wt,
                                          const float* __restrict__ bias)
{
    const int tid = threadIdx.x;
    const int o = tid % DOUT;
    const int g = tid / DOUT;

    if constexpr (TPG >= 4) {
        constexpr int NP = TPG / 2;
        unsigned long long acc[NP];
        #pragma unroll
        for (int p = 0; p < NP; p++) acc[p] = pack2(0.0f, 0.0f);
        #pragma unroll 4
        for (int k = 0; k < DIN; k++) {
            const float w = wt[k * DOUT + o];
            const unsigned long long w2 = pack2(w, w);
            const ulonglong2* zr = (const ulonglong2*)(zin + k * TOKP + g * TPG);
            #pragma unroll
            for (int p = 0; p < TPG / 4; p++) {
                ulonglong2 u = zr[p];
                acc[2 * p]     = fma2(w2, u.x, acc[2 * p]);
                acc[2 * p + 1] = fma2(w2, u.y, acc[2 * p + 1]);
            }
        }
        const float bv = bias[o];
        float* orow = zout + o * TOKP + g * TPG;
        #pragma unroll
        for (int p = 0; p < NP; p++) {
            float2 v = unpack2(acc[p]);
            v.x += bv; v.y += bv;
            if (LEAKY) { v.x = fmaxf(v.x, 0.01f * v.x); v.y = fmaxf(v.y, 0.01f * v.y); }
            orow[2 * p] = v.x; orow[2 * p + 1] = v.y;
        }
    } else if constexpr (TPG == 2) {
        unsigned long long acc = pack2(0.0f, 0.0f);
        #pragma unroll 4
        for (int k = 0; k < DIN; k++) {
            const float w = wt[k * DOUT + o];
            unsigned long long u = *(const unsigned long long*)(zin + k * TOKP + g * 2);
            acc = fma2(pack2(w, w), u, acc);
        }
        const float bv = bias[o];
        float2 v = unpack2(acc);
        v.x += bv; v.y += bv;
        if (LEAKY) { v.x = fmaxf(v.x, 0.01f * v.x); v.y = fmaxf(v.y, 0.01f * v.y); }
        float* orow = zout + o * TOKP + g * 2;
        orow[0] = v.x; orow[1] = v.y;
    }
}

// ---------------- RNN side ------------------------------------------------------
__device__ void rnn_cta(const float* __restrict__ W_hh, float* __restrict__ out,
                        float* sm, int b)
{
    float* ws  = sm;                         // NT2*WTST
    float* xws = sm + NT2 * WTST;            // 2 x CH*HH
    float* hb  = xws + 2 * CH * HH;          // 2*HBUF
    const int tid = threadIdx.x;
    const int w = tid >> 5, lane = tid & 31;
    const int g = lane >> 2, rr = lane & 3;
    const int j0 = w * 32 + rr * 8;
    const int myrow = j0 + g;
    const int hoff = HPAD * (myrow >> 5) + (myrow & 31);
    const bool g0b = (g & 1) != 0;
    const bool g1b = (g & 2) != 0;
    const bool g2b = (g & 4) != 0;

    // register weights: 8 rows x 24 k (12 ull each)
    unsigned long long wr[8][RKU];
    #pragma unroll
    for (int r = 0; r < 8; r++) {
        const ulonglong2* src = (const ulonglong2*)(W_hh + (j0 + r) * HH + g * 32);
        #pragma unroll
        for (int i = 0; i < RKU / 2; i++) {
            ulonglong2 u = src[i];
            wr[r][2 * i] = u.x; wr[r][2 * i + 1] = u.y;
        }
    }
    // smem weights: 8 rows x 8 k (k_rel 24..31)
    float* wsm = ws + tid * WTST;
    #pragma unroll
    for (int r = 0; r < 8; r++) {
        const float4* gsrc = (const float4*)(W_hh + (j0 + r) * HH + g * 32 + 24);
        float4* d = (float4*)(wsm + r * SWF);
        d[0] = gsrc[0]; d[1] = gsrc[1];
    }

    for (int idx = tid; idx < 2 * HBUF; idx += NT2) hb[idx] = 0.0f;

    const float* xg = g_xw + (size_t)b * TT * HH;
    float* hout = g_ht + (size_t)b * TT * HH;
    const uint32_t xw_sbase = (uint32_t)__cvta_generic_to_shared(xws);

    // prologue: stage chunks 0 and 1 (CH*HH = 8192 fl = 2048 float4)
    #pragma unroll
    for (int i = 0; i < 8; i++)
        cpa16(xw_sbase + (uint32_t)(tid + i * NT2) * 16,
              (const float4*)xg + tid + i * NT2);
    cpa_commit();
    #pragma unroll
    for (int i = 0; i < 8; i++)
        cpa16(xw_sbase + (uint32_t)(CH * HH / 4 + tid + i * NT2) * 16,
              (const float4*)(xg + CH * HH) + tid + i * NT2);
    cpa_commit();

    int buf = 0;
    float hl = 0.0f;
    const ulonglong2* wk = (const ulonglong2*)wsm;

    for (int c = 0; c < NCH; c++) {
        if (c >= NCH - 2) { asm volatile("cp.async.wait_group 0;" ::: "memory"); }
        else              { asm volatile("cp.async.wait_group 1;" ::: "memory"); }
        __syncthreads();
        const float* xwc = xws + (c & 1) * (CH * HH);

        for (int s = 0; s < CH; s++) {
            const float xwv = xwc[s * HH + myrow];

            // h for this k-group: 32 floats = 8 ull2 (conflict-free, 4-lane bcast)
            const ulonglong2* h2 = (const ulonglong2*)(hb + buf * HBUF + HPAD * g);
            unsigned long long hu[16];
            #pragma unroll
            for (int i = 0; i < 8; i++) {
                ulonglong2 u = h2[i];
                hu[2 * i] = u.x; hu[2 * i + 1] = u.y;
            }

            unsigned long long acc[8];
            #pragma unroll
            for (int r = 0; r < 8; r++) acc[r] = pack2(0.f, 0.f);
            #pragma unroll
            for (int i = 0; i < RKU; i++) {
                #pragma unroll
                for (int r = 0; r < 8; r++)
                    acc[r] = fma2(wr[r][i], hu[i], acc[r]);
            }
            #pragma unroll
            for (int r = 0; r < 8; r++) {          // k_rel 24..31 from smem
                ulonglong2 wa = wk[2 * r];
                ulonglong2 wb = wk[2 * r + 1];
                acc[r] = fma2(wa.x, hu[12], acc[r]);
                acc[r] = fma2(wa.y, hu[13], acc[r]);
                acc[r] = fma2(wb.x, hu[14], acc[r]);
                acc[r] = fma2(wb.y, hu[15], acc[r]);
            }

            float p[8];
            #pragma unroll
            for (int r = 0; r < 8; r++) {
                float2 v = unpack2(acc[r]);
                p[r] = v.x + v.y;
            }

            // 3-stage reduce-scatter: lane (rr,g) ends with row j0+g.
            float q[4];
            #pragma unroll
            for (int rp = 0; rp < 4; rp++) {
                float snd = g0b ? p[2 * rp] : p[2 * rp + 1];
                float o = __shfl_xor_sync(0xFFFFFFFFu, snd, 4);
                q[rp] = (g0b ? p[2 * rp + 1] : p[2 * rp]) + o;
            }
            float u0, u1;
            {
                float snd = g1b ? q[0] : q[1];
                float o = __shfl_xor_sync(0xFFFFFFFFu, snd, 8);
                u0 = (g1b ? q[1] : q[0]) + o;
                float snd2 = g1b ? q[2] : q[3];
                float o2 = __shfl_xor_sync(0xFFFFFFFFu, snd2, 8);
                u1 = (g1b ? q[3] : q[2]) + o2;
            }
            float sd;
            {
                float snd = g2b ? u0 : u1;
                float o = __shfl_xor_sync(0xFFFFFFFFu, snd, 16);
                sd = (g2b ? u1 : u0) + o;
            }

            const float hn = fast_tanh(sd + xwv);
            hb[(buf ^ 1) * HBUF + hoff] = hn;
            hout[(size_t)(c * CH + s) * HH + myrow] = hn;
            hl = hn;
            __syncthreads();
            buf ^= 1;
        }

        if (tid == 0) st_release(&g_prog[b], (c + 1) * CH);

        if (c + 2 < NCH) {
            const float4* gb = (const float4*)(xg + (size_t)(c + 2) * CH * HH);
            const uint32_t sb = xw_sbase + (uint32_t)((c & 1) * CH * HH) * 4;
            #pragma unroll
            for (int i = 0; i < 8; i++)
                cpa16(sb + (uint32_t)(tid + i * NT2) * 16, gb + tid + i * NT2);
            cpa_commit();
        }
    }
    out[(size_t)BB * TT * II + (size_t)b * HH + myrow] = hl;
    asm volatile("cp.async.wait_group 0;" ::: "memory");
    __syncthreads();
}

// ---------------- MLP worker ----------------------------------------------------
__device__ void mlp_worker(
    const float* __restrict__ x,
    const float* __restrict__ b0, const float* __restrict__ b1,
    const float* __restrict__ b2, const float* __restrict__ b3,
    const float* __restrict__ b4, const float* __restrict__ b5,
    const float* __restrict__ b6, float* __restrict__ out,
    float* sm)
{
    __shared__ int s_blk;
    float* bufA = sm;
    float* bufB = sm + 264 * TOKP;
    const int tid = threadIdx.x;

    for (;;) {
        __syncthreads();
        if (tid == 0) s_blk = atomicAdd(&g_tick, 1);
        __syncthreads();
        const int blk = s_blk;
        if (blk >= 64 * BB) return;
        const int tc = blk >> 6;       // chunk of 64 steps
        const int b = blk & 63;        // chain
        const int need = (tc + 1) * 64;

        if (tid == 0) {
            while (ld_acquire(&g_prog[b]) < need) __nanosleep(128);
        }
        __syncthreads();

        const size_t tok0 = (size_t)b * TT + (size_t)tc * TOKN;

        for (int idx = tid; idx < TOKN * 256; idx += NT2) {
            const int tk = idx >> 8, jj = idx & 255;
            bufA[jj * TOKP + tk] = g_ht[(tok0 + tk) * HH + jj];
        }
        for (int idx = tid; idx < TOKN * 5; idx += NT2) {
            const int tk = idx / 5, i = idx - tk * 5;
            bufA[(256 + i) * TOKP + tk] = x[(tok0 + tk) * XD + II + i];
        }
        __syncthreads();

        mlp_layer<256, 261, 64, true>(bufA, bufB, g_wt + OFF0, b0); __syncthreads();
        mlp_layer<128, 256, 32, true>(bufB, bufA, g_wt + OFF1, b1); __syncthreads();
        mlp_layer< 64, 128, 16, true>(bufA, bufB, g_wt + OFF2, b2); __syncthreads();
        mlp_layer< 32,  64,  8, true>(bufB, bufA, g_wt + OFF3, b3); __syncthreads();
        mlp_layer< 16,  32,  4, true>(bufA, bufB, g_wt + OFF4, b4); __syncthreads();
        mlp_layer<  8,  16,  2, true>(bufB, bufA, g_wt + OFF5, b5); __syncthreads();

        {
            const int o = tid & 7, g0 = tid >> 3;   // g0 in [0,32)
            if (o < 7) {
                #pragma unroll
                for (int g = g0; g < TOKN; g += 32) {
                    float acc = b6[o];
                    #pragma unroll
                    for (int k = 0; k < 8; k++)
                        acc = fmaf(g_wt[OFF6 + k * 7 + o], bufA[k * TOKP + g], acc);
                    out[(tok0 + g) * II + o] = acc;
                }
            }
        }
    }
}

// ---------------- fused kernel --------------------------------------------------
__global__ __launch_bounds__(NT2, 1) void fused_kernel(
    const float* __restrict__ x, const float* __restrict__ W_hh,
    const float* __restrict__ b0, const float* __restrict__ b1,
    const float* __restrict__ b2, const float* __restrict__ b3,
    const float* __restrict__ b4, const float* __restrict__ b5,
    const float* __restrict__ b6, float* __restrict__ out)
{
    extern __shared__ float sm[];
    if (blockIdx.x < NRNN) {
        rnn_cta(W_hh, out, sm, blockIdx.x);
        // chain finished -> join the MLP pool on this SM
        mlp_worker(x, b0, b1, b2, b3, b4, b5, b6, out, sm);
    } else {
        mlp_worker(x, b0, b1, b2, b3, b4, b5, b6, out, sm);
    }
}

// ---------------- xW precompute -------------------------------------------------
__global__ void xw_kernel(const float* __restrict__ x, const float* __restrict__ W_ih,
                          const float* __restrict__ b_ih, const float* __restrict__ b_hh)
{
    const int stride = gridDim.x * blockDim.x;
    for (size_t idx = (size_t)blockIdx.x * blockDim.x + threadIdx.x;
         idx < (size_t)BB * TT * HH; idx += stride) {
        const size_t tok = idx >> 8;
        const int j = (int)(idx & 255);
        const float* xr = x + tok * XD;
        float acc = b_ih[j] + b_hh[j];
        #pragma unroll
        for (int i = 0; i < II; i++) acc = fmaf(xr[i], W_ih[j * II + i], acc);
        g_xw[idx] = acc;
    }
}

// ---------------- prep ----------------------------------------------------------
__global__ void prep_kernel(const float* __restrict__ W0, const float* __restrict__ W1,
                            const float* __restrict__ W2, const float* __restrict__ W3,
                            const float* __restrict__ W4, const float* __restrict__ W5,
                            const float* __restrict__ W6)
{
    if (blockIdx.x == 0) {
        if (threadIdx.x < BB) g_prog[threadIdx.x] = 0;
        if (threadIdx.x == 0) g_tick = 0;
    }
    const float* Ws[7] = {W0, W1, W2, W3, W4, W5, W6};
    const int douts[7] = {256, 128, 64, 32, 16, 8, 7};
    const int dins[7]  = {261, 256, 128, 64, 32, 16, 8};
    int off = 0;
    const int stride = gridDim.x * blockDim.x;
    const int tid0 = blockIdx.x * blockDim.x + threadIdx.x;
    for (int l = 0; l < 7; l++) {
        const int dout = douts[l], din = dins[l], n = dout * din;
        const float* W = Ws[l];
        for (int idx = tid0; idx < n; idx += stride) {
            const int k = idx / dout, o = idx - k * dout;
            g_wt[off + idx] = W[o * din + k];
        }
        off += n;
    }
}

// ---------------- launch --------------------------------------------------------
extern "C" void kernel_launch(void* const* d_in, const int* in_sizes, int n_in,
                              void* d_out, int out_size)
{
    const float* x    = (const float*)d_in[0];
    const float* W_ih = (const float*)d_in[1];
    const float* W_hh = (const float*)d_in[2];
    const float* b_ih = (const float*)d_in[3];
    const float* b_hh = (const float*)d_in[4];
    const float* W[7];
    const float* bb[7];
    for (int i = 0; i < 7; i++) {
        W[i]  = (const float*)d_in[5 + 2 * i];
        bb[i] = (const float*)d_in[6 + 2 * i];
    }
    float* out = (float*)d_out;

    static int inited = 0;
    if (!inited) {
        cudaFuncSetAttribute(fused_kernel,
                             cudaFuncAttributeMaxDynamicSharedMemorySize, FUSED_SMEM_B);
        inited = 1;
    }

    prep_kernel<<<64, 256>>>(W[0], W[1], W[2], W[3], W[4], W[5], W[6]);
    xw_kernel<<<512, 256>>>(x, W_ih, b_ih, b_hh);
    fused_kernel<<<NCTA, NT2, FUSED_SMEM_B>>>(x, W_hh,
                                              bb[0], bb[1], bb[2], bb[3],
                                              bb[4], bb[5], bb[6], out);
}

// round 11
// speedup vs baseline: 1.4715x; 1.0011x over previous
#include <cuda_runtime.h>
#include <cstdint>
#include <math.h>

// Problem dims
#define BB 64
#define TT 4096
#define HH 256
#define II 7
#define XD 12   // I + F

#define NRNN 64
#define NWORK 84
#define NCTA (NRNN + NWORK)
#define NT2 256

// ---------------- device scratch ----------------------------------------------
__device__ float g_ht[(size_t)BB * TT * HH];   // RNN hidden states (256 MB)
__device__ float g_xw[(size_t)BB * TT * HH];   // precomputed xW + biases (256 MB)
__device__ float g_wt[110520];                 // transposed MLP weights
__device__ int   g_prog[BB];                   // RNN progress per chain
__device__ int   g_tick;                       // MLP chunk ticket counter

// MLP layer offsets in g_wt
#define OFF0 0
#define OFF1 66816
#define OFF2 99584
#define OFF3 107776
#define OFF4 109824
#define OFF5 110336
#define OFF6 110464

// ---------------- helpers ------------------------------------------------------
__device__ __forceinline__ unsigned long long fma2(unsigned long long a,
                                                   unsigned long long b,
                                                   unsigned long long c) {
    unsigned long long d;
    asm("fma.rn.f32x2 %0, %1, %2, %3;" : "=l"(d) : "l"(a), "l"(b), "l"(c));
    return d;
}
__device__ __forceinline__ unsigned long long pack2(float lo, float hi) {
    unsigned long long d;
    asm("mov.b64 %0, {%1, %2};" : "=l"(d) : "f"(lo), "f"(hi));
    return d;
}
__device__ __forceinline__ float2 unpack2(unsigned long long v) {
    float lo, hi;
    asm("mov.b64 {%0, %1}, %2;" : "=f"(lo), "=f"(hi) : "l"(v));
    return make_float2(lo, hi);
}
__device__ __forceinline__ int ld_acquire(const int* p) {
    int v;
    asm volatile("ld.global.acquire.gpu.b32 %0, [%1];" : "=r"(v) : "l"(p));
    return v;
}
__device__ __forceinline__ void st_release(int* p, int v) {
    asm volatile("st.global.release.gpu.b32 [%0], %1;" :: "l"(p), "r"(v));
}
__device__ __forceinline__ float fast_tanh(float x) {
    float e = __expf(2.0f * x);
    return 1.0f - __fdividef(2.0f, e + 1.0f);
}
__device__ __forceinline__ void cpa16(uint32_t s, const void* g) {
    asm volatile("cp.async.cg.shared.global [%0], [%1], 16;" :: "r"(s), "l"(g));
}
__device__ __forceinline__ void cpa_commit() {
    asm volatile("cp.async.commit_group;" ::: "memory");
}

// ---------------- RNN config ---------------------------------------------------
// 256 threads, one CTA per chain. warp w = tid>>5; lane: g = lane>>2 (k-group of
// 32 k), rr = lane&3. Thread: rows j0..j0+7 (j0 = w*32 + rr*8), k in [g*32,+32).
// Per row: 26 weight floats (13 ull, pairs 0..12) in regs, 6 (pairs 13..15) smem.
#define RKU 13        // reg ulls per row
#define WROW 8        // smem weight row stride (floats: pair13 @0, pairs14-15 @4)
#define WTST 68       // per-thread smem weight stride (64 used + 4 pad)
#define HPAD 36       // h group stride (32 used + 4 pad) -> conflict-free
#define HBUF 288      // h buffer stride (8*HPAD)
#define CH 32         // xw chunk (steps)
#define NCH (TT / CH) // 128

// smem: weights 256*68=17408 | xw 2*CH*HH=16384 | h 2*HBUF=576 => 34368 fl
#define RNN_SMF (NT2 * WTST + 2 * CH * HH + 2 * HBUF)

// ---------------- MLP config ---------------------------------------------------
#define TOKN 64
#define TOKP 68
#define MLP_SMF ((264 + 256) * TOKP)                   // 35360 fl = 141440 B
#define FUSED_SMEM_B (MLP_SMF * 4)

template<int DOUT, int DIN, int TPG, bool LEAKY>
__device__ __forceinline__ void mlp_layer(const float* __restrict__ zin,
                                          float* __restrict__ zout,
                                          const float* __restrict__ wt,
                                          const float* __restrict__ bias)
{
    const int tid = threadIdx.x;
    const int o = tid % DOUT;
    const int g = tid / DOUT;

    if constexpr (TPG >= 4) {
        constexpr int NP = TPG / 2;
        unsigned long long acc[NP];
        #pragma unroll
        for (int p = 0; p < NP; p++) acc[p] = pack2(0.0f, 0.0f);
        #pragma unroll 4
        for (int k = 0; k < DIN; k++) {
            const float w = wt[k * DOUT + o];
            const unsigned long long w2 = pack2(w, w);
            const ulonglong2* zr = (const ulonglong2*)(zin + k * TOKP + g * TPG);
            #pragma unroll
            for (int p = 0; p < TPG / 4; p++) {
                ulonglong2 u = zr[p];
                acc[2 * p]     = fma2(w2, u.x, acc[2 * p]);
                acc[2 * p + 1] = fma2(w2, u.y, acc[2 * p + 1]);
            }
        }
        const float bv = bias[o];
        float* orow = zout + o * TOKP + g * TPG;
        #pragma unroll
        for (int p = 0; p < NP; p++) {
            float2 v = unpack2(acc[p]);
            v.x += bv; v.y += bv;
            if (LEAKY) { v.x = fmaxf(v.x, 0.01f * v.x); v.y = fmaxf(v.y, 0.01f * v.y); }
            orow[2 * p] = v.x; orow[2 * p + 1] = v.y;
        }
    } else if constexpr (TPG == 2) {
        unsigned long long acc = pack2(0.0f, 0.0f);
        #pragma unroll 4
        for (int k = 0; k < DIN; k++) {
            const float w = wt[k * DOUT + o];
            unsigned long long u = *(const unsigned long long*)(zin + k * TOKP + g * 2);
            acc = fma2(pack2(w, w), u, acc);
        }
        const float bv = bias[o];
        float2 v = unpack2(acc);
        v.x += bv; v.y += bv;
        if (LEAKY) { v.x = fmaxf(v.x, 0.01f * v.x); v.y = fmaxf(v.y, 0.01f * v.y); }
        float* orow = zout + o * TOKP + g * 2;
        orow[0] = v.x; orow[1] = v.y;
    }
}

// ---------------- RNN side ------------------------------------------------------
__device__ void rnn_cta(const float* __restrict__ W_hh, float* __restrict__ out,
                        float* sm, int b)
{
    float* ws  = sm;                         // NT2*WTST
    float* xws = sm + NT2 * WTST;            // 2 x CH*HH
    float* hb  = xws + 2 * CH * HH;          // 2*HBUF
    const int tid = threadIdx.x;
    const int w = tid >> 5, lane = tid & 31;
    const int g = lane >> 2, rr = lane & 3;
    const int j0 = w * 32 + rr * 8;
    const int myrow = j0 + g;
    const int hoff = HPAD * (myrow >> 5) + (myrow & 31);
    const bool g0b = (g & 1) != 0;
    const bool g1b = (g & 2) != 0;
    const bool g2b = (g & 4) != 0;

    // register weights: 8 rows x 26 k (13 ull each, pairs 0..12)
    unsigned long long wr[8][RKU];
    #pragma unroll
    for (int r = 0; r < 8; r++) {
        const float* row = W_hh + (j0 + r) * HH + g * 32;
        const ulonglong2* src = (const ulonglong2*)row;
        #pragma unroll
        for (int i = 0; i < 6; i++) {
            ulonglong2 u = src[i];
            wr[r][2 * i] = u.x; wr[r][2 * i + 1] = u.y;
        }
        wr[r][12] = *(const unsigned long long*)(row + 24);
    }
    // smem weights: 8 rows x 6 k (pairs 13,14,15 = k_rel 26..31)
    float* wsm = ws + tid * WTST;
    #pragma unroll
    for (int r = 0; r < 8; r++) {
        const float* row = W_hh + (j0 + r) * HH + g * 32;
        // pair 13 (k26,27) at fl offset r*WROW (8B-aligned)
        *(unsigned long long*)(wsm + r * WROW) =
            *(const unsigned long long*)(row + 26);
        // pairs 14,15 (k28..31) at fl offset r*WROW+4 (16B-aligned)
        *(ulonglong2*)(wsm + r * WROW + 4) =
            *(const ulonglong2*)(row + 28);
    }

    for (int idx = tid; idx < 2 * HBUF; idx += NT2) hb[idx] = 0.0f;

    const float* xg = g_xw + (size_t)b * TT * HH;
    float* hout = g_ht + (size_t)b * TT * HH;
    const uint32_t xw_sbase = (uint32_t)__cvta_generic_to_shared(xws);

    // prologue: stage chunks 0 and 1 (CH*HH = 8192 fl = 2048 float4)
    #pragma unroll
    for (int i = 0; i < 8; i++)
        cpa16(xw_sbase + (uint32_t)(tid + i * NT2) * 16,
              (const float4*)xg + tid + i * NT2);
    cpa_commit();
    #pragma unroll
    for (int i = 0; i < 8; i++)
        cpa16(xw_sbase + (uint32_t)(CH * HH / 4 + tid + i * NT2) * 16,
              (const float4*)(xg + CH * HH) + tid + i * NT2);
    cpa_commit();

    int buf = 0;
    float hl = 0.0f;

    for (int c = 0; c < NCH; c++) {
        if (c >= NCH - 2) { asm volatile("cp.async.wait_group 0;" ::: "memory"); }
        else              { asm volatile("cp.async.wait_group 1;" ::: "memory"); }
        __syncthreads();
        const float* xwc = xws + (c & 1) * (CH * HH);

        for (int s = 0; s < CH; s++) {
            const float xwv = xwc[s * HH + myrow];
            const ulonglong2* h2 = (const ulonglong2*)(hb + buf * HBUF + HPAD * g);

            unsigned long long acc[8];
            #pragma unroll
            for (int r = 0; r < 8; r++) acc[r] = pack2(0.f, 0.f);

            // pairs 0..11: register weights, h consumed per-LDS (live = 1 ull2)
            #pragma unroll
            for (int i = 0; i < 6; i++) {
                ulonglong2 u = h2[i];
                #pragma unroll
                for (int r = 0; r < 8; r++) {
                    acc[r] = fma2(wr[r][2 * i],     u.x, acc[r]);
                    acc[r] = fma2(wr[r][2 * i + 1], u.y, acc[r]);
                }
            }
            // pairs 12 (reg) + 13 (smem)
            {
                ulonglong2 u = h2[6];
                #pragma unroll
                for (int r = 0; r < 8; r++)
                    acc[r] = fma2(wr[r][12], u.x, acc[r]);
                #pragma unroll
                for (int r = 0; r < 8; r++) {
                    unsigned long long w13 =
                        *(const unsigned long long*)(wsm + r * WROW);
                    acc[r] = fma2(w13, u.y, acc[r]);
                }
            }
            // pairs 14,15 (smem)
            {
                ulonglong2 u = h2[7];
                #pragma unroll
                for (int r = 0; r < 8; r++) {
                    ulonglong2 wv = *(const ulonglong2*)(wsm + r * WROW + 4);
                    acc[r] = fma2(wv.x, u.x, acc[r]);
                    acc[r] = fma2(wv.y, u.y, acc[r]);
                }
            }

            float p[8];
            #pragma unroll
            for (int r = 0; r < 8; r++) {
                float2 v = unpack2(acc[r]);
                p[r] = v.x + v.y;
            }

            // 3-stage reduce-scatter: lane (rr,g) ends with row j0+g.
            float q[4];
            #pragma unroll
            for (int rp = 0; rp < 4; rp++) {
                float snd = g0b ? p[2 * rp] : p[2 * rp + 1];
                float o = __shfl_xor_sync(0xFFFFFFFFu, snd, 4);
                q[rp] = (g0b ? p[2 * rp + 1] : p[2 * rp]) + o;
            }
            float u0, u1;
            {
                float snd = g1b ? q[0] : q[1];
                float o = __shfl_xor_sync(0xFFFFFFFFu, snd, 8);
                u0 = (g1b ? q[1] : q[0]) + o;
                float snd2 = g1b ? q[2] : q[3];
                float o2 = __shfl_xor_sync(0xFFFFFFFFu, snd2, 8);
                u1 = (g1b ? q[3] : q[2]) + o2;
            }
            float sd;
            {
                float snd = g2b ? u0 : u1;
                float o = __shfl_xor_sync(0xFFFFFFFFu, snd, 16);
                sd = (g2b ? u1 : u0) + o;
            }

            const float hn = fast_tanh(sd + xwv);
            hb[(buf ^ 1) * HBUF + hoff] = hn;
            hout[(size_t)(c * CH + s) * HH + myrow] = hn;
            hl = hn;
            __syncthreads();
            buf ^= 1;
        }

        if (tid == 0) st_release(&g_prog[b], (c + 1) * CH);

        if (c + 2 < NCH) {
            const float4* gb = (const float4*)(xg + (size_t)(c + 2) * CH * HH);
            const uint32_t sb = xw_sbase + (uint32_t)((c & 1) * CH * HH) * 4;
            #pragma unroll
            for (int i = 0; i < 8; i++)
                cpa16(sb + (uint32_t)(tid + i * NT2) * 16, gb + tid + i * NT2);
            cpa_commit();
        }
    }
    out[(size_t)BB * TT * II + (size_t)b * HH + myrow] = hl;
    asm volatile("cp.async.wait_group 0;" ::: "memory");
    __syncthreads();
}

// ---------------- MLP worker ----------------------------------------------------
__device__ void mlp_worker(
    const float* __restrict__ x,
    const float* __restrict__ b0, const float* __restrict__ b1,
    const float* __restrict__ b2, const float* __restrict__ b3,
    const float* __restrict__ b4, const float* __restrict__ b5,
    const float* __restrict__ b6, float* __restrict__ out,
    float* sm)
{
    __shared__ int s_blk;
    float* bufA = sm;
    float* bufB = sm + 264 * TOKP;
    const int tid = threadIdx.x;

    for (;;) {
        __syncthreads();
        if (tid == 0) s_blk = atomicAdd(&g_tick, 1);
        __syncthreads();
        const int blk = s_blk;
        if (blk >= 64 * BB) return;
        const int tc = blk >> 6;       // chunk of 64 steps
        const int b = blk & 63;        // chain
        const int need = (tc + 1) * 64;

        if (tid == 0) {
            while (ld_acquire(&g_prog[b]) < need) __nanosleep(128);
        }
        __syncthreads();

        const size_t tok0 = (size_t)b * TT + (size_t)tc * TOKN;

        for (int idx = tid; idx < TOKN * 256; idx += NT2) {
            const int tk = idx >> 8, jj = idx & 255;
            bufA[jj * TOKP + tk] = g_ht[(tok0 + tk) * HH + jj];
        }
        for (int idx = tid; idx < TOKN * 5; idx += NT2) {
            const int tk = idx / 5, i = idx - tk * 5;
            bufA[(256 + i) * TOKP + tk] = x[(tok0 + tk) * XD + II + i];
        }
        __syncthreads();

        mlp_layer<256, 261, 64, true>(bufA, bufB, g_wt + OFF0, b0); __syncthreads();
        mlp_layer<128, 256, 32, true>(bufB, bufA, g_wt + OFF1, b1); __syncthreads();
        mlp_layer< 64, 128, 16, true>(bufA, bufB, g_wt + OFF2, b2); __syncthreads();
        mlp_layer< 32,  64,  8, true>(bufB, bufA, g_wt + OFF3, b3); __syncthreads();
        mlp_layer< 16,  32,  4, true>(bufA, bufB, g_wt + OFF4, b4); __syncthreads();
        mlp_layer<  8,  16,  2, true>(bufB, bufA, g_wt + OFF5, b5); __syncthreads();

        {
            const int o = tid & 7, g0 = tid >> 3;   // g0 in [0,32)
            if (o < 7) {
                #pragma unroll
                for (int g = g0; g < TOKN; g += 32) {
                    float acc = b6[o];
                    #pragma unroll
                    for (int k = 0; k < 8; k++)
                        acc = fmaf(g_wt[OFF6 + k * 7 + o], bufA[k * TOKP + g], acc);
                    out[(tok0 + g) * II + o] = acc;
                }
            }
        }
    }
}

// ---------------- fused kernel --------------------------------------------------
__global__ __launch_bounds__(NT2, 1) void fused_kernel(
    const float* __restrict__ x, const float* __restrict__ W_hh,
    const float* __restrict__ b0, const float* __restrict__ b1,
    const float* __restrict__ b2, const float* __restrict__ b3,
    const float* __restrict__ b4, const float* __restrict__ b5,
    const float* __restrict__ b6, float* __restrict__ out)
{
    extern __shared__ float sm[];
    if (blockIdx.x < NRNN) {
        rnn_cta(W_hh, out, sm, blockIdx.x);
        // chain finished -> join the MLP pool on this SM
        mlp_worker(x, b0, b1, b2, b3, b4, b5, b6, out, sm);
    } else {
        mlp_worker(x, b0, b1, b2, b3, b4, b5, b6, out, sm);
    }
}

// ---------------- xW precompute -------------------------------------------------
__global__ void xw_kernel(const float* __restrict__ x, const float* __restrict__ W_ih,
                          const float* __restrict__ b_ih, const float* __restrict__ b_hh)
{
    const int stride = gridDim.x * blockDim.x;
    for (size_t idx = (size_t)blockIdx.x * blockDim.x + threadIdx.x;
         idx < (size_t)BB * TT * HH; idx += stride) {
        const size_t tok = idx >> 8;
        const int j = (int)(idx & 255);
        const float* xr = x + tok * XD;
        float acc = b_ih[j] + b_hh[j];
        #pragma unroll
        for (int i = 0; i < II; i++) acc = fmaf(xr[i], W_ih[j * II + i], acc);
        g_xw[idx] = acc;
    }
}

// ---------------- prep ----------------------------------------------------------
__global__ void prep_kernel(const float* __restrict__ W0, const float* __restrict__ W1,
                            const float* __restrict__ W2, const float* __restrict__ W3,
                            const float* __restrict__ W4, const float* __restrict__ W5,
                            const float* __restrict__ W6)
{
    if (blockIdx.x == 0) {
        if (threadIdx.x < BB) g_prog[threadIdx.x] = 0;
        if (threadIdx.x == 0) g_tick = 0;
    }
    const float* Ws[7] = {W0, W1, W2, W3, W4, W5, W6};
    const int douts[7] = {256, 128, 64, 32, 16, 8, 7};
    const int dins[7]  = {261, 256, 128, 64, 32, 16, 8};
    int off = 0;
    const int stride = gridDim.x * blockDim.x;
    const int tid0 = blockIdx.x * blockDim.x + threadIdx.x;
    for (int l = 0; l < 7; l++) {
        const int dout = douts[l], din = dins[l], n = dout * din;
        const float* W = Ws[l];
        for (int idx = tid0; idx < n; idx += stride) {
            const int k = idx / dout, o = idx - k * dout;
            g_wt[off + idx] = W[o * din + k];
        }
        off += n;
    }
}

// ---------------- launch --------------------------------------------------------
extern "C" void kernel_launch(void* const* d_in, const int* in_sizes, int n_in,
                              void* d_out, int out_size)
{
    const float* x    = (const float*)d_in[0];
    const float* W_ih = (const float*)d_in[1];
    const float* W_hh = (const float*)d_in[2];
    const float* b_ih = (const float*)d_in[3];
    const float* b_hh = (const float*)d_in[4];
    const float* W[7];
    const float* bb[7];
    for (int i = 0; i < 7; i++) {
        W[i]  = (const float*)d_in[5 + 2 * i];
        bb[i] = (const float*)d_in[6 + 2 * i];
    }
    float* out = (float*)d_out;

    static int inited = 0;
    if (!inited) {
        cudaFuncSetAttribute(fused_kernel,
                             cudaFuncAttributeMaxDynamicSharedMemorySize, FUSED_SMEM_B);
        inited = 1;
    }

    prep_kernel<<<64, 256>>>(W[0], W[1], W[2], W[3], W[4], W[5], W[6]);
    xw_kernel<<<512, 256>>>(x, W_ih, b_ih, b_hh);
    fused_kernel<<<NCTA, NT2, FUSED_SMEM_B>>>(x, W_hh,
                                              bb[0], bb[1], bb[2], bb[3],
                                              bb[4], bb[5], bb[6], out);
}